// round 14
// baseline (speedup 1.0000x reference)
#include <cuda_runtime.h>
#include <cstdint>

#define NN    65536          // B*N nodes
#define EDG   1048576        // B*EPER edges
#define SLOTS 64             // max adjacency slots per node
#define C3    384
#define NHEAD 5
#define NCENT 15             // HEADS*KC
#define AGG_GRID 2048

// ---------------- scratch (static __device__, no allocations) ----------------
__device__ int    d_in_cnt[NN];
__device__ int    d_out_cnt[NN];
__device__ int    d_in_list[NN * SLOTS];
__device__ int    d_out_list[NN * SLOTS];
__device__ float  d_m[(size_t)NN * 128];
__device__ float  d_X[(size_t)NN * C3];
__device__ float  d_Sf[(size_t)NN * 4];
__device__ float  d_val[NN];
__device__ int    d_amax[NN];
__device__ float  d_psum[(size_t)C3 * AGG_GRID];
__device__ float  d_psq [(size_t)C3 * AGG_GRID];
__device__ float  d_a[C3], d_bb[C3];
__device__ float  d_knorm[NCENT];
__device__ float  d_scal[8];

// ---------------- packed f32x2 helpers (Blackwell FFMA2) ----------------
__device__ __forceinline__ unsigned long long pack2(float lo, float hi) {
    unsigned long long r;
    asm("mov.b64 %0, {%1, %2};" : "=l"(r) : "f"(lo), "f"(hi));
    return r;
}
__device__ __forceinline__ void ffma2(unsigned long long& acc,
                                      unsigned long long a, unsigned long long b) {
    asm("fma.rn.f32x2 %0, %1, %2, %0;" : "+l"(acc) : "l"(a), "l"(b));
}
// ---------------- cp.async helpers ----------------
__device__ __forceinline__ uint32_t su32(const void* p) {
    return (uint32_t)__cvta_generic_to_shared(p);
}
__device__ __forceinline__ void cpa16(uint32_t s, const void* g) {
    asm volatile("cp.async.cg.shared.global [%0], [%1], 16;" :: "r"(s), "l"(g));
}
#define CP_COMMIT() asm volatile("cp.async.commit_group;")
#define CP_WAIT(N)  asm volatile("cp.async.wait_group %0;" :: "n"(N))

// ---------------- kernels ----------------
__global__ void k_zero1() {
    int i = blockIdx.x * 256 + threadIdx.x;
    if (i < NN) { d_in_cnt[i] = 0; d_out_cnt[i] = 0; }
}
__global__ void k_zs() {
    if (threadIdx.x < 8) d_scal[threadIdx.x] = 0.f;
}

__global__ void k_fill(const int* __restrict__ ei) {
    const int* src = ei;
    const int* dst = ei + EDG;
    for (int e = blockIdx.x * blockDim.x + threadIdx.x; e < EDG;
         e += gridDim.x * blockDim.x) {
        int s = src[e] & (NN - 1);
        int d = dst[e] & (NN - 1);
        int sl = atomicAdd(&d_in_cnt[d], 1);
        if (sl < SLOTS) d_in_list[d * SLOTS + sl] = s;
        int s2 = atomicAdd(&d_out_cnt[s], 1);
        if (s2 < SLOTS) d_out_list[s * SLOTS + s2] = d;
    }
}

// m = A(65536x128) @ W(128x128). BM=128, BN=128, BK=16, 8x8 FFMA2 tile,
// cp.async double-buffered.
__global__ void __launch_bounds__(256, 2)
k_gemm(const float* __restrict__ Aext, int mode, const float* __restrict__ W) {
    __shared__ float4 Asb[2][4 * 128];
    __shared__ float  Wsb[2][16 * 132];
    const float* A;
    int lda;
    if (mode == 0)      { A = Aext;      lda = 128; }
    else if (mode == 1) { A = d_X;       lda = C3;  }
    else                { A = d_X + 128; lda = C3;  }

    int tid  = threadIdx.x;
    int row0 = blockIdx.x * 128;
    int tr   = tid >> 4;
    int tc   = tid & 15;

    int ra  = tid & 127;
    int ga  = tid >> 7;
    int wr0 = tid >> 5;
    int wc0 = (tid & 31) * 4;

    const float* Arow = A + (size_t)(row0 + ra) * lda + ga * 4;

    unsigned long long acc[8][4];
#pragma unroll
    for (int i = 0; i < 8; i++)
#pragma unroll
        for (int j = 0; j < 4; j++) acc[i][j] = 0ull;

#define ISSUE(kc, buf)                                                        \
    do {                                                                      \
        const float* g0 = Arow + (kc) * 16;                                   \
        cpa16(su32(&Asb[buf][ga * 128 + ra]), g0);                            \
        cpa16(su32(&Asb[buf][(ga + 2) * 128 + ra]), g0 + 8);                  \
        cpa16(su32(&Wsb[buf][wr0 * 132 + wc0]),                               \
              W + (size_t)((kc) * 16 + wr0) * 128 + wc0);                     \
        cpa16(su32(&Wsb[buf][(wr0 + 8) * 132 + wc0]),                         \
              W + (size_t)((kc) * 16 + wr0 + 8) * 128 + wc0);                 \
        CP_COMMIT();                                                          \
    } while (0)

    ISSUE(0, 0);

#pragma unroll
    for (int kc = 0; kc < 8; kc++) {
        if (kc < 7) { ISSUE(kc + 1, (kc + 1) & 1); CP_WAIT(1); }
        else        { CP_WAIT(0); }
        __syncthreads();

        const float4* ab = Asb[kc & 1];
        const float*  wb = Wsb[kc & 1];
#pragma unroll
        for (int g = 0; g < 4; g++) {
            float4 a[8];
#pragma unroll
            for (int i = 0; i < 8; i++) a[i] = ab[g * 128 + tr * 8 + i];
#pragma unroll
            for (int k2 = 0; k2 < 4; k2++) {
                const float* wrow = wb + (g * 4 + k2) * 132 + tc * 8;
                ulonglong2 w01 = *(const ulonglong2*)wrow;
                ulonglong2 w23 = *(const ulonglong2*)(wrow + 4);
#pragma unroll
                for (int i = 0; i < 8; i++) {
                    float av = (k2 == 0) ? a[i].x : (k2 == 1) ? a[i].y
                             : (k2 == 2) ? a[i].z : a[i].w;
                    unsigned long long aa = pack2(av, av);
                    ffma2(acc[i][0], aa, w01.x);
                    ffma2(acc[i][1], aa, w01.y);
                    ffma2(acc[i][2], aa, w23.x);
                    ffma2(acc[i][3], aa, w23.y);
                }
            }
        }
        __syncthreads();
    }
#undef ISSUE

#pragma unroll
    for (int i = 0; i < 8; i++) {
        float* o = d_m + (size_t)(row0 + tr * 8 + i) * 128 + tc * 8;
        ulonglong2 u0, u1;
        u0.x = acc[i][0]; u0.y = acc[i][1];
        u1.x = acc[i][2]; u1.y = acc[i][3];
        *(ulonglong2*)o       = u0;
        *(ulonglong2*)(o + 4) = u1;
    }
}

// agg[dst] = relu(sum_{src in list(dst)} m[src] + b). Warp per node.
__global__ void k_agg(const float* __restrict__ bias, int chBase) {
    __shared__ float bsum[8][128];
    __shared__ float bsq [8][128];
    int wid = threadIdx.x >> 5, lane = threadIdx.x & 31;
    int warpG = blockIdx.x * 8 + wid;
    int totW  = gridDim.x * 8;
    float4 bv = *(const float4*)(bias + lane * 4);
    const float4* m4 = (const float4*)d_m;
    float s0 = 0, s1 = 0, s2 = 0, s3 = 0, q0 = 0, q1 = 0, q2 = 0, q3 = 0;

    for (int node = warpG; node < NN; node += totW) {
        int raw = d_in_cnt[node];
        int cnt = raw < SLOTS ? raw : SLOTS;
        const int* lst = d_in_list + (size_t)node * SLOTS;
        int i0 = (lane < cnt)      ? lst[lane]      : 0;
        int i1 = (32 + lane < cnt) ? lst[32 + lane] : 0;

        float4 a0 = {0,0,0,0}, a1 = {0,0,0,0}, a2 = {0,0,0,0}, a3 = {0,0,0,0};
        int c1 = cnt < 32 ? cnt : 32;
        int j = 0;
        for (; j + 4 <= c1; j += 4) {
            int t0 = __shfl_sync(0xffffffffu, i0, j);
            int t1 = __shfl_sync(0xffffffffu, i0, j + 1);
            int t2 = __shfl_sync(0xffffffffu, i0, j + 2);
            int t3 = __shfl_sync(0xffffffffu, i0, j + 3);
            float4 v0 = m4[(size_t)t0 * 32 + lane];
            float4 v1 = m4[(size_t)t1 * 32 + lane];
            float4 v2 = m4[(size_t)t2 * 32 + lane];
            float4 v3 = m4[(size_t)t3 * 32 + lane];
            a0.x += v0.x; a0.y += v0.y; a0.z += v0.z; a0.w += v0.w;
            a1.x += v1.x; a1.y += v1.y; a1.z += v1.z; a1.w += v1.w;
            a2.x += v2.x; a2.y += v2.y; a2.z += v2.z; a2.w += v2.w;
            a3.x += v3.x; a3.y += v3.y; a3.z += v3.z; a3.w += v3.w;
        }
        for (; j < c1; j++) {
            int t0 = __shfl_sync(0xffffffffu, i0, j);
            float4 v0 = m4[(size_t)t0 * 32 + lane];
            a0.x += v0.x; a0.y += v0.y; a0.z += v0.z; a0.w += v0.w;
        }
        for (int j2 = 32; j2 < cnt; j2++) {
            int t0 = __shfl_sync(0xffffffffu, i1, j2 - 32);
            float4 v0 = m4[(size_t)t0 * 32 + lane];
            a1.x += v0.x; a1.y += v0.y; a1.z += v0.z; a1.w += v0.w;
        }
        float4 o;
        o.x = fmaxf(a0.x + a1.x + a2.x + a3.x + bv.x, 0.f);
        o.y = fmaxf(a0.y + a1.y + a2.y + a3.y + bv.y, 0.f);
        o.z = fmaxf(a0.z + a1.z + a2.z + a3.z + bv.z, 0.f);
        o.w = fmaxf(a0.w + a1.w + a2.w + a3.w + bv.w, 0.f);
        *(float4*)(d_X + (size_t)node * C3 + chBase + lane * 4) = o;
        s0 += o.x; s1 += o.y; s2 += o.z; s3 += o.w;
        q0 = fmaf(o.x, o.x, q0); q1 = fmaf(o.y, o.y, q1);
        q2 = fmaf(o.z, o.z, q2); q3 = fmaf(o.w, o.w, q3);
    }
    bsum[wid][lane * 4 + 0] = s0; bsum[wid][lane * 4 + 1] = s1;
    bsum[wid][lane * 4 + 2] = s2; bsum[wid][lane * 4 + 3] = s3;
    bsq [wid][lane * 4 + 0] = q0; bsq [wid][lane * 4 + 1] = q1;
    bsq [wid][lane * 4 + 2] = q2; bsq [wid][lane * 4 + 3] = q3;
    __syncthreads();
    if (threadIdx.x < 128) {
        int ch = threadIdx.x;
        float ts = 0.f, tq = 0.f;
#pragma unroll
        for (int w = 0; w < 8; w++) { ts += bsum[w][ch]; tq += bsq[w][ch]; }
        d_psum[(size_t)(chBase + ch) * AGG_GRID + blockIdx.x] = ts;
        d_psq [(size_t)(chBase + ch) * AGG_GRID + blockIdx.x] = tq;
    }
}

// BN stats (deterministic) + affine; block 48: centroid norms.
__global__ void k_bn(const float* __restrict__ gamma, const float* __restrict__ beta,
                     const float* __restrict__ kmat) {
    int wid = threadIdx.x >> 5, lane = threadIdx.x & 31;
    if (blockIdx.x < 48) {
        int ch = blockIdx.x * 8 + wid;
        const float* ps = d_psum + (size_t)ch * AGG_GRID;
        const float* pq = d_psq  + (size_t)ch * AGG_GRID;
        float s = 0.f, q = 0.f;
#pragma unroll
        for (int i = 0; i < AGG_GRID / 32; i++) {
            s += ps[lane + i * 32];
            q += pq[lane + i * 32];
        }
#pragma unroll
        for (int off = 16; off; off >>= 1) {
            s += __shfl_xor_sync(0xffffffffu, s, off);
            q += __shfl_xor_sync(0xffffffffu, q, off);
        }
        if (lane == 0) {
            double mu  = (double)s * (1.0 / NN);
            double var = (double)q * (1.0 / NN) - mu * mu;
            float  a   = gamma[ch] * (float)(1.0 / sqrt(var + 1e-5));
            d_a[ch]  = a;
            d_bb[ch] = beta[ch] - (float)mu * a;
        }
    } else {
        for (int j = wid; j < NCENT; j += 8) {
            float s = 0.f;
            for (int c = lane; c < C3; c += 32) {
                float v = kmat[j * C3 + c];
                s = fmaf(v, v, s);
            }
#pragma unroll
            for (int off = 16; off; off >>= 1)
                s += __shfl_xor_sync(0xffffffffu, s, off);
            if (lane == 0) d_knorm[j] = s;
        }
    }
}

// per-node soft assignment S. float4 channel layout (conflict-free LDS.128,
// coalesced LDG.128) + smem-transpose reduction.
__global__ void k_dist(const float* __restrict__ kmat) {
    __shared__ float4 k2s[NCENT * 96];        // [j][seg*32+lane]
    __shared__ float4 a_s4[96], bb_s4[96];
    __shared__ float  kn_s[NCENT];
    __shared__ float  tr[8][32][17];
    __shared__ float  fin[8][16];
    for (int i = threadIdx.x; i < NCENT * 96; i += 256) {
        int j = i / 96, w = i - j * 96;
        k2s[i] = *(const float4*)(kmat + j * C3 + w * 4);
    }
    if (threadIdx.x < 96) {
        a_s4 [threadIdx.x] = *(const float4*)(d_a  + threadIdx.x * 4);
        bb_s4[threadIdx.x] = *(const float4*)(d_bb + threadIdx.x * 4);
    }
    if (threadIdx.x < NCENT) kn_s[threadIdx.x] = d_knorm[threadIdx.x];
    __syncthreads();

    int wid = threadIdx.x >> 5, lane = threadIdx.x & 31;
    int warpG = blockIdx.x * 8 + wid;
    int totW  = gridDim.x * 8;

    float4 av[3], bv[3];
#pragma unroll
    for (int seg = 0; seg < 3; seg++) {
        av[seg] = a_s4 [seg * 32 + lane];
        bv[seg] = bb_s4[seg * 32 + lane];
    }

    for (int node = warpG; node < NN; node += totW) {
        const float* xr = d_X + (size_t)node * C3;
        float4 xn[3];
        float nrm = 0.f;
#pragma unroll
        for (int seg = 0; seg < 3; seg++) {
            float4 xv = *(const float4*)(xr + seg * 128 + lane * 4);
            xn[seg].x = fmaf(xv.x, av[seg].x, bv[seg].x);
            xn[seg].y = fmaf(xv.y, av[seg].y, bv[seg].y);
            xn[seg].z = fmaf(xv.z, av[seg].z, bv[seg].z);
            xn[seg].w = fmaf(xv.w, av[seg].w, bv[seg].w);
            nrm = fmaf(xn[seg].x, xn[seg].x, nrm);
            nrm = fmaf(xn[seg].y, xn[seg].y, nrm);
            nrm = fmaf(xn[seg].z, xn[seg].z, nrm);
            nrm = fmaf(xn[seg].w, xn[seg].w, nrm);
        }
        float red[16];
        red[15] = nrm;
#pragma unroll
        for (int j = 0; j < NCENT; j++) {
            const float4* kr = k2s + j * 96;
            float d = 0.f;
#pragma unroll
            for (int seg = 0; seg < 3; seg++) {
                float4 kv = kr[seg * 32 + lane];
                d = fmaf(kv.x, xn[seg].x, d);
                d = fmaf(kv.y, xn[seg].y, d);
                d = fmaf(kv.z, xn[seg].z, d);
                d = fmaf(kv.w, xn[seg].w, d);
            }
            red[j] = d;
        }
        // transpose-reduce: lane partials -> smem -> 2-lane column sums
#pragma unroll
        for (int v = 0; v < 16; v++) tr[wid][lane][v] = red[v];
        __syncwarp();
        {
            int half = lane >> 4, v = lane & 15;
            float s = 0.f;
#pragma unroll
            for (int i = 0; i < 16; i++) s += tr[wid][half * 16 + i][v];
            s += __shfl_xor_sync(0xffffffffu, s, 16);
            if (lane < 16) fin[wid][lane] = s;
        }
        __syncwarp();
        if (lane == 0) {
            float nt = fin[wid][15];
            float S0 = 0.f, S1 = 0.f, S2 = 0.f;
#pragma unroll
            for (int h = 0; h < NHEAD; h++) {
                float dd[3];
#pragma unroll
                for (int kk = 0; kk < 3; kk++) {
                    int j = h * 3 + kk;
                    float d2 = fmaxf(kn_s[j] + nt - 2.f * fin[wid][j], 0.f);
                    dd[kk] = 1.f / (1.f + d2);
                }
                float inv = 1.f / (dd[0] + dd[1] + dd[2]);
                S0 += dd[0] * inv; S1 += dd[1] * inv; S2 += dd[2] * inv;
            }
            float* o = d_Sf + (size_t)node * 4;
            o[0] = S0; o[1] = S1; o[2] = S2; o[3] = 0.f;
        }
        __syncwarp();
    }
}

// Sagg gather (by src), deg, softmax, argmax, loss contributions.
__global__ void k_S2(const int* __restrict__ y) {
    __shared__ float rs[5][256];
    int i = blockIdx.x * 256 + threadIdx.x;
    float sl = 0.f, c0 = 0.f, c1 = 0.f, A0 = 0.f, A1 = 0.f;
    {
        int oc  = d_out_cnt[i];
        int cnt = oc < SLOTS ? oc : SLOTS;
        const int* lst = d_out_list + (size_t)i * SLOTS;
        const float4* Sf4 = (const float4*)d_Sf;
        float r0 = 0.f, r1 = 0.f, r2 = 0.f;
#pragma unroll 4
        for (int j = 0; j < cnt; j++) {
            float4 s = Sf4[lst[j]];
            r0 += s.x; r1 += s.y; r2 += s.z;
        }
        int ic = d_in_cnt[i];
        float deg = 0.5f * (float)(oc + ic);
        if (deg == 0.f) deg = 1.f;
        float inv = 1.f / deg;
        r0 *= inv; r1 *= inv; r2 *= inv;
        int am = 0; float mx = r0;
        if (r1 > mx) { am = 1; mx = r1; }
        if (r2 > mx) { am = 2; mx = r2; }
        float val = 1.f / (expf(r0 - mx) + expf(r1 - mx) + expf(r2 - mx));
        d_amax[i] = am;
        d_val[i]  = val;
        if (am < 2) {
            sl = val;
            int yb = y[i >> 9];
            float ce = log1pf(expf(val)) - (yb == am ? val : 0.f);
            if (yb == 0) { c0 = 1.f; A0 = ce; } else { c1 = 1.f; A1 = ce; }
        }
    }
    int t = threadIdx.x;
    rs[0][t] = sl; rs[1][t] = c0; rs[2][t] = c1; rs[3][t] = A0; rs[4][t] = A1;
    __syncthreads();
    for (int s = 128; s > 0; s >>= 1) {
        if (t < s) {
#pragma unroll
            for (int r = 0; r < 5; r++) rs[r][t] += rs[r][t + s];
        }
        __syncthreads();
    }
    if (t < 5) atomicAdd(&d_scal[t], rs[t][0]);
}

// per-graph pooling + classification head + (block 0) loss, fused.
__global__ void k_pool(const float* __restrict__ Wp,
                       const float* __restrict__ W1, const float* __restrict__ b1,
                       const float* __restrict__ W2, const float* __restrict__ b2,
                       float* __restrict__ out, int lossIdx) {
    int b = blockIdx.x, t = threadIdx.x;
    __shared__ float vals[512];
    __shared__ int   ams[512];
    __shared__ float xp[2][C3];
    __shared__ float xf[32];
    __shared__ float h[128];
    __shared__ float lg[2];
    for (int n = t; n < 512; n += 384) {
        vals[n] = d_val [b * 512 + n];
        ams[n]  = d_amax[b * 512 + n];
    }
    __syncthreads();
    float ac = d_a[t], bc = d_bb[t];
    float acc0 = 0.f, acc1 = 0.f;
    const float* Xb = d_X + (size_t)b * 512 * C3 + t;
#pragma unroll 8
    for (int n = 0; n < 512; n++) {
        float x  = Xb[(size_t)n * C3];
        float v  = vals[n];
        int   am = ams[n];
        float xn = fmaf(x, ac, bc);
        if (am == 0)      acc0 = fmaf(v, xn, acc0);
        else if (am == 1) acc1 = fmaf(v, xn, acc1);
    }
    xp[0][t] = acc0; xp[1][t] = acc1;
    __syncthreads();
    if (t < 32) {
        int kk = t >> 4, o = t & 15;
        float s = 0.f;
        for (int c = 0; c < C3; c++) s = fmaf(xp[kk][c], Wp[c * 16 + o], s);
        xf[t] = s;
    }
    __syncthreads();
    if (t < 128) {
        float acc = b1[t];
#pragma unroll
        for (int i = 0; i < 32; i++) acc = fmaf(xf[i], W1[i * 128 + t], acc);
        h[t] = fmaxf(acc, 0.f);
    }
    __syncthreads();
    if (t < 64) {
        int c = t >> 5, l = t & 31;
        float p = 0.f;
        for (int j = l; j < 128; j += 32) p = fmaf(h[j], W2[j * 2 + c], p);
#pragma unroll
        for (int off = 16; off; off >>= 1) p += __shfl_xor_sync(0xffffffffu, p, off);
        if (l == 0) lg[c] = p + b2[c];
    }
    __syncthreads();
    if (t == 0) {
        float m   = fmaxf(lg[0], lg[1]);
        float lse = m + logf(expf(lg[0] - m) + expf(lg[1] - m));
        out[b * 2 + 0] = lg[0] - lse;
        out[b * 2 + 1] = lg[1] - lse;
    }
    if (b == 0 && t == 256) {
        float sl = d_scal[0], c0 = d_scal[1], c1 = d_scal[2];
        float A0 = d_scal[3], A1 = d_scal[4];
        float bc0 = 1.f + c0, bc1 = 1.f + c1;
        float wm  = fmaxf(bc0, bc1);
        float w0  = wm / (bc0 + 0.001f), w1 = wm / (bc1 + 0.001f);
        float den = fmaxf(w0 * c0 + w1 * c1, 1e-12f);
        float cel = (w0 * A0 + w1 * A1) / den;
        out[lossIdx] = 10.f * cel + 0.01f * (sl * (1.f / 128.f));
    }
}

// ---------------- launch ----------------
extern "C" void kernel_launch(void* const* d_in, const int* in_sizes, int n_in,
                              void* d_out, int out_size) {
    const float* x     = (const float*)d_in[0];
    const int*   ei    = (const int*)d_in[1];
    const int*   y     = (const int*)d_in[2];
    const float* W1    = (const float*)d_in[3];
    const float* b1    = (const float*)d_in[4];
    const float* W2    = (const float*)d_in[5];
    const float* b2    = (const float*)d_in[6];
    const float* W3    = (const float*)d_in[7];
    const float* b3    = (const float*)d_in[8];
    const float* gamma = (const float*)d_in[9];
    const float* beta  = (const float*)d_in[10];
    const float* kmat  = (const float*)d_in[11];
    const float* Wp    = (const float*)d_in[12];
    const float* l1W   = (const float*)d_in[13];
    const float* l1b   = (const float*)d_in[14];
    const float* l2W   = (const float*)d_in[15];
    const float* l2b   = (const float*)d_in[16];
    float* out = (float*)d_out;

    // Capture slot is launch #4 -> PROBE k_pool there (stale-but-deterministic
    // inputs; every output it writes is overwritten by the real k_pool below).
    k_zero1<<<256, 256>>>();                       // 1
    k_fill<<<2048, 256>>>(ei);                     // 2
    k_zs<<<1, 32>>>();                             // 3
    k_pool<<<128, 384>>>(Wp, l1W, l1b, l2W, l2b, out, out_size - 1);  // 4 <- probe

    k_gemm<<<512, 256>>>(x, 0, W1);                // 5
    k_agg<<<AGG_GRID, 256>>>(b1, 0);               // 6
    k_gemm<<<512, 256>>>(x, 1, W2);                // 7
    k_agg<<<AGG_GRID, 256>>>(b2, 128);             // 8
    k_gemm<<<512, 256>>>(x, 2, W3);                // 9
    k_agg<<<AGG_GRID, 256>>>(b3, 256);             // 10

    k_bn<<<49, 256>>>(gamma, beta, kmat);          // 11
    k_dist<<<2048, 256>>>(kmat);                   // 12
    k_S2<<<256, 256>>>(y);                         // 13
    k_pool<<<128, 384>>>(Wp, l1W, l1b, l2W, l2b, out, out_size - 1);  // 14 (real)
}

// round 15
// speedup vs baseline: 1.9229x; 1.9229x over previous
#include <cuda_runtime.h>
#include <cstdint>

#define NN    65536          // B*N nodes
#define EDG   1048576        // B*EPER edges
#define SLOTS 64             // max adjacency slots per node
#define C3    384
#define NHEAD 5
#define NCENT 15             // HEADS*KC
#define AGG_GRID 2048

// ---------------- scratch (static __device__, no allocations) ----------------
__device__ int    d_in_cnt[NN];
__device__ int    d_out_cnt[NN];
__device__ int    d_in_list[NN * SLOTS];
__device__ int    d_out_list[NN * SLOTS];
__device__ float  d_m[(size_t)NN * 128];
__device__ float  d_X[(size_t)NN * C3];
__device__ float  d_Sf[(size_t)NN * 4];
__device__ float  d_val[NN];
__device__ int    d_amax[NN];
__device__ float  d_psum[(size_t)C3 * AGG_GRID];
__device__ float  d_psq [(size_t)C3 * AGG_GRID];
__device__ float  d_xpart[128 * 2 * 4 * C3];   // pooling partials [b][k][q][c]
__device__ float  d_a[C3], d_bb[C3];
__device__ float  d_knorm[NCENT];
__device__ float  d_scal[8];

// ---------------- packed f32x2 helpers (Blackwell FFMA2) ----------------
__device__ __forceinline__ unsigned long long pack2(float lo, float hi) {
    unsigned long long r;
    asm("mov.b64 %0, {%1, %2};" : "=l"(r) : "f"(lo), "f"(hi));
    return r;
}
__device__ __forceinline__ void ffma2(unsigned long long& acc,
                                      unsigned long long a, unsigned long long b) {
    asm("fma.rn.f32x2 %0, %1, %2, %0;" : "+l"(acc) : "l"(a), "l"(b));
}
// ---------------- cp.async helpers ----------------
__device__ __forceinline__ uint32_t su32(const void* p) {
    return (uint32_t)__cvta_generic_to_shared(p);
}
__device__ __forceinline__ void cpa16(uint32_t s, const void* g) {
    asm volatile("cp.async.cg.shared.global [%0], [%1], 16;" :: "r"(s), "l"(g));
}
#define CP_COMMIT() asm volatile("cp.async.commit_group;")
#define CP_WAIT(N)  asm volatile("cp.async.wait_group %0;" :: "n"(N))

// ---------------- kernels ----------------
__global__ void k_zero1() {
    int i = blockIdx.x * 256 + threadIdx.x;
    if (i < NN) { d_in_cnt[i] = 0; d_out_cnt[i] = 0; }
}
__global__ void k_zs() {
    if (threadIdx.x < 8) d_scal[threadIdx.x] = 0.f;
}

__global__ void k_fill(const int* __restrict__ ei) {
    const int* src = ei;
    const int* dst = ei + EDG;
    for (int e = blockIdx.x * blockDim.x + threadIdx.x; e < EDG;
         e += gridDim.x * blockDim.x) {
        int s = src[e] & (NN - 1);
        int d = dst[e] & (NN - 1);
        int sl = atomicAdd(&d_in_cnt[d], 1);
        if (sl < SLOTS) d_in_list[d * SLOTS + sl] = s;
        int s2 = atomicAdd(&d_out_cnt[s], 1);
        if (s2 < SLOTS) d_out_list[s * SLOTS + s2] = d;
    }
}

// m = A(65536x128) @ W(128x128). BM=128, BN=128, BK=16, 8x8 FFMA2 tile,
// cp.async double-buffered.
__global__ void __launch_bounds__(256, 2)
k_gemm(const float* __restrict__ Aext, int mode, const float* __restrict__ W) {
    __shared__ float4 Asb[2][4 * 128];
    __shared__ float  Wsb[2][16 * 132];
    const float* A;
    int lda;
    if (mode == 0)      { A = Aext;      lda = 128; }
    else if (mode == 1) { A = d_X;       lda = C3;  }
    else                { A = d_X + 128; lda = C3;  }

    int tid  = threadIdx.x;
    int row0 = blockIdx.x * 128;
    int tr   = tid >> 4;
    int tc   = tid & 15;

    int ra  = tid & 127;
    int ga  = tid >> 7;
    int wr0 = tid >> 5;
    int wc0 = (tid & 31) * 4;

    const float* Arow = A + (size_t)(row0 + ra) * lda + ga * 4;

    unsigned long long acc[8][4];
#pragma unroll
    for (int i = 0; i < 8; i++)
#pragma unroll
        for (int j = 0; j < 4; j++) acc[i][j] = 0ull;

#define ISSUE(kc, buf)                                                        \
    do {                                                                      \
        const float* g0 = Arow + (kc) * 16;                                   \
        cpa16(su32(&Asb[buf][ga * 128 + ra]), g0);                            \
        cpa16(su32(&Asb[buf][(ga + 2) * 128 + ra]), g0 + 8);                  \
        cpa16(su32(&Wsb[buf][wr0 * 132 + wc0]),                               \
              W + (size_t)((kc) * 16 + wr0) * 128 + wc0);                     \
        cpa16(su32(&Wsb[buf][(wr0 + 8) * 132 + wc0]),                         \
              W + (size_t)((kc) * 16 + wr0 + 8) * 128 + wc0);                 \
        CP_COMMIT();                                                          \
    } while (0)

    ISSUE(0, 0);

#pragma unroll
    for (int kc = 0; kc < 8; kc++) {
        if (kc < 7) { ISSUE(kc + 1, (kc + 1) & 1); CP_WAIT(1); }
        else        { CP_WAIT(0); }
        __syncthreads();

        const float4* ab = Asb[kc & 1];
        const float*  wb = Wsb[kc & 1];
#pragma unroll
        for (int g = 0; g < 4; g++) {
            float4 a[8];
#pragma unroll
            for (int i = 0; i < 8; i++) a[i] = ab[g * 128 + tr * 8 + i];
#pragma unroll
            for (int k2 = 0; k2 < 4; k2++) {
                const float* wrow = wb + (g * 4 + k2) * 132 + tc * 8;
                ulonglong2 w01 = *(const ulonglong2*)wrow;
                ulonglong2 w23 = *(const ulonglong2*)(wrow + 4);
#pragma unroll
                for (int i = 0; i < 8; i++) {
                    float av = (k2 == 0) ? a[i].x : (k2 == 1) ? a[i].y
                             : (k2 == 2) ? a[i].z : a[i].w;
                    unsigned long long aa = pack2(av, av);
                    ffma2(acc[i][0], aa, w01.x);
                    ffma2(acc[i][1], aa, w01.y);
                    ffma2(acc[i][2], aa, w23.x);
                    ffma2(acc[i][3], aa, w23.y);
                }
            }
        }
        __syncthreads();
    }
#undef ISSUE

#pragma unroll
    for (int i = 0; i < 8; i++) {
        float* o = d_m + (size_t)(row0 + tr * 8 + i) * 128 + tc * 8;
        ulonglong2 u0, u1;
        u0.x = acc[i][0]; u0.y = acc[i][1];
        u1.x = acc[i][2]; u1.y = acc[i][3];
        *(ulonglong2*)o       = u0;
        *(ulonglong2*)(o + 4) = u1;
    }
}

// agg[dst] = relu(sum_{src in list(dst)} m[src] + b). Warp per node.
__global__ void k_agg(const float* __restrict__ bias, int chBase) {
    __shared__ float bsum[8][128];
    __shared__ float bsq [8][128];
    int wid = threadIdx.x >> 5, lane = threadIdx.x & 31;
    int warpG = blockIdx.x * 8 + wid;
    int totW  = gridDim.x * 8;
    float4 bv = *(const float4*)(bias + lane * 4);
    const float4* m4 = (const float4*)d_m;
    float s0 = 0, s1 = 0, s2 = 0, s3 = 0, q0 = 0, q1 = 0, q2 = 0, q3 = 0;

    for (int node = warpG; node < NN; node += totW) {
        int raw = d_in_cnt[node];
        int cnt = raw < SLOTS ? raw : SLOTS;
        const int* lst = d_in_list + (size_t)node * SLOTS;
        int i0 = (lane < cnt)      ? lst[lane]      : 0;
        int i1 = (32 + lane < cnt) ? lst[32 + lane] : 0;

        float4 a0 = {0,0,0,0}, a1 = {0,0,0,0}, a2 = {0,0,0,0}, a3 = {0,0,0,0};
        int c1 = cnt < 32 ? cnt : 32;
        int j = 0;
        for (; j + 4 <= c1; j += 4) {
            int t0 = __shfl_sync(0xffffffffu, i0, j);
            int t1 = __shfl_sync(0xffffffffu, i0, j + 1);
            int t2 = __shfl_sync(0xffffffffu, i0, j + 2);
            int t3 = __shfl_sync(0xffffffffu, i0, j + 3);
            float4 v0 = m4[(size_t)t0 * 32 + lane];
            float4 v1 = m4[(size_t)t1 * 32 + lane];
            float4 v2 = m4[(size_t)t2 * 32 + lane];
            float4 v3 = m4[(size_t)t3 * 32 + lane];
            a0.x += v0.x; a0.y += v0.y; a0.z += v0.z; a0.w += v0.w;
            a1.x += v1.x; a1.y += v1.y; a1.z += v1.z; a1.w += v1.w;
            a2.x += v2.x; a2.y += v2.y; a2.z += v2.z; a2.w += v2.w;
            a3.x += v3.x; a3.y += v3.y; a3.z += v3.z; a3.w += v3.w;
        }
        for (; j < c1; j++) {
            int t0 = __shfl_sync(0xffffffffu, i0, j);
            float4 v0 = m4[(size_t)t0 * 32 + lane];
            a0.x += v0.x; a0.y += v0.y; a0.z += v0.z; a0.w += v0.w;
        }
        for (int j2 = 32; j2 < cnt; j2++) {
            int t0 = __shfl_sync(0xffffffffu, i1, j2 - 32);
            float4 v0 = m4[(size_t)t0 * 32 + lane];
            a1.x += v0.x; a1.y += v0.y; a1.z += v0.z; a1.w += v0.w;
        }
        float4 o;
        o.x = fmaxf(a0.x + a1.x + a2.x + a3.x + bv.x, 0.f);
        o.y = fmaxf(a0.y + a1.y + a2.y + a3.y + bv.y, 0.f);
        o.z = fmaxf(a0.z + a1.z + a2.z + a3.z + bv.z, 0.f);
        o.w = fmaxf(a0.w + a1.w + a2.w + a3.w + bv.w, 0.f);
        *(float4*)(d_X + (size_t)node * C3 + chBase + lane * 4) = o;
        s0 += o.x; s1 += o.y; s2 += o.z; s3 += o.w;
        q0 = fmaf(o.x, o.x, q0); q1 = fmaf(o.y, o.y, q1);
        q2 = fmaf(o.z, o.z, q2); q3 = fmaf(o.w, o.w, q3);
    }
    bsum[wid][lane * 4 + 0] = s0; bsum[wid][lane * 4 + 1] = s1;
    bsum[wid][lane * 4 + 2] = s2; bsum[wid][lane * 4 + 3] = s3;
    bsq [wid][lane * 4 + 0] = q0; bsq [wid][lane * 4 + 1] = q1;
    bsq [wid][lane * 4 + 2] = q2; bsq [wid][lane * 4 + 3] = q3;
    __syncthreads();
    if (threadIdx.x < 128) {
        int ch = threadIdx.x;
        float ts = 0.f, tq = 0.f;
#pragma unroll
        for (int w = 0; w < 8; w++) { ts += bsum[w][ch]; tq += bsq[w][ch]; }
        d_psum[(size_t)(chBase + ch) * AGG_GRID + blockIdx.x] = ts;
        d_psq [(size_t)(chBase + ch) * AGG_GRID + blockIdx.x] = tq;
    }
}

// BN stats (deterministic) + affine; block 48: centroid norms.
__global__ void k_bn(const float* __restrict__ gamma, const float* __restrict__ beta,
                     const float* __restrict__ kmat) {
    int wid = threadIdx.x >> 5, lane = threadIdx.x & 31;
    if (blockIdx.x < 48) {
        int ch = blockIdx.x * 8 + wid;
        const float* ps = d_psum + (size_t)ch * AGG_GRID;
        const float* pq = d_psq  + (size_t)ch * AGG_GRID;
        float s = 0.f, q = 0.f;
#pragma unroll
        for (int i = 0; i < AGG_GRID / 32; i++) {
            s += ps[lane + i * 32];
            q += pq[lane + i * 32];
        }
#pragma unroll
        for (int off = 16; off; off >>= 1) {
            s += __shfl_xor_sync(0xffffffffu, s, off);
            q += __shfl_xor_sync(0xffffffffu, q, off);
        }
        if (lane == 0) {
            double mu  = (double)s * (1.0 / NN);
            double var = (double)q * (1.0 / NN) - mu * mu;
            float  a   = gamma[ch] * (float)(1.0 / sqrt(var + 1e-5));
            d_a[ch]  = a;
            d_bb[ch] = beta[ch] - (float)mu * a;
        }
    } else {
        for (int j = wid; j < NCENT; j += 8) {
            float s = 0.f;
            for (int c = lane; c < C3; c += 32) {
                float v = kmat[j * C3 + c];
                s = fmaf(v, v, s);
            }
#pragma unroll
            for (int off = 16; off; off >>= 1)
                s += __shfl_xor_sync(0xffffffffu, s, off);
            if (lane == 0) d_knorm[j] = s;
        }
    }
}

// per-node soft assignment S. float4 channel layout + node-ahead prefetch
// + smem-transpose reduction.
__global__ void k_dist(const float* __restrict__ kmat) {
    __shared__ float4 k2s[NCENT * 96];
    __shared__ float4 a_s4[96], bb_s4[96];
    __shared__ float  kn_s[NCENT];
    __shared__ float  tr[8][32][17];
    __shared__ float  fin[8][16];
    for (int i = threadIdx.x; i < NCENT * 96; i += 256) {
        int j = i / 96, w = i - j * 96;
        k2s[i] = *(const float4*)(kmat + j * C3 + w * 4);
    }
    if (threadIdx.x < 96) {
        a_s4 [threadIdx.x] = *(const float4*)(d_a  + threadIdx.x * 4);
        bb_s4[threadIdx.x] = *(const float4*)(d_bb + threadIdx.x * 4);
    }
    if (threadIdx.x < NCENT) kn_s[threadIdx.x] = d_knorm[threadIdx.x];
    __syncthreads();

    int wid = threadIdx.x >> 5, lane = threadIdx.x & 31;
    int warpG = blockIdx.x * 8 + wid;
    int totW  = gridDim.x * 8;

    float4 av[3], bv[3];
#pragma unroll
    for (int seg = 0; seg < 3; seg++) {
        av[seg] = a_s4 [seg * 32 + lane];
        bv[seg] = bb_s4[seg * 32 + lane];
    }

    float4 xv[3];
    {
        const float* xr = d_X + (size_t)warpG * C3;
#pragma unroll
        for (int seg = 0; seg < 3; seg++)
            xv[seg] = *(const float4*)(xr + seg * 128 + lane * 4);
    }

    for (int node = warpG; node < NN; node += totW) {
        int nxt = node + totW;
        float4 xn[3];
        float nrm = 0.f;
#pragma unroll
        for (int seg = 0; seg < 3; seg++) {
            xn[seg].x = fmaf(xv[seg].x, av[seg].x, bv[seg].x);
            xn[seg].y = fmaf(xv[seg].y, av[seg].y, bv[seg].y);
            xn[seg].z = fmaf(xv[seg].z, av[seg].z, bv[seg].z);
            xn[seg].w = fmaf(xv[seg].w, av[seg].w, bv[seg].w);
            nrm = fmaf(xn[seg].x, xn[seg].x, nrm);
            nrm = fmaf(xn[seg].y, xn[seg].y, nrm);
            nrm = fmaf(xn[seg].z, xn[seg].z, nrm);
            nrm = fmaf(xn[seg].w, xn[seg].w, nrm);
        }
        // prefetch next node's X before the heavy centroid reduction
        if (nxt < NN) {
            const float* xr = d_X + (size_t)nxt * C3;
#pragma unroll
            for (int seg = 0; seg < 3; seg++)
                xv[seg] = *(const float4*)(xr + seg * 128 + lane * 4);
        }
        float red[16];
        red[15] = nrm;
#pragma unroll
        for (int j = 0; j < NCENT; j++) {
            const float4* kr = k2s + j * 96;
            float d = 0.f;
#pragma unroll
            for (int seg = 0; seg < 3; seg++) {
                float4 kv = kr[seg * 32 + lane];
                d = fmaf(kv.x, xn[seg].x, d);
                d = fmaf(kv.y, xn[seg].y, d);
                d = fmaf(kv.z, xn[seg].z, d);
                d = fmaf(kv.w, xn[seg].w, d);
            }
            red[j] = d;
        }
#pragma unroll
        for (int v = 0; v < 16; v++) tr[wid][lane][v] = red[v];
        __syncwarp();
        {
            int half = lane >> 4, v = lane & 15;
            float s = 0.f;
#pragma unroll
            for (int i = 0; i < 16; i++) s += tr[wid][half * 16 + i][v];
            s += __shfl_xor_sync(0xffffffffu, s, 16);
            if (lane < 16) fin[wid][lane] = s;
        }
        __syncwarp();
        if (lane == 0) {
            float nt = fin[wid][15];
            float S0 = 0.f, S1 = 0.f, S2 = 0.f;
#pragma unroll
            for (int h = 0; h < NHEAD; h++) {
                float dd[3];
#pragma unroll
                for (int kk = 0; kk < 3; kk++) {
                    int j = h * 3 + kk;
                    float d2 = fmaxf(kn_s[j] + nt - 2.f * fin[wid][j], 0.f);
                    dd[kk] = 1.f / (1.f + d2);
                }
                float inv = 1.f / (dd[0] + dd[1] + dd[2]);
                S0 += dd[0] * inv; S1 += dd[1] * inv; S2 += dd[2] * inv;
            }
            float* o = d_Sf + (size_t)node * 4;
            o[0] = S0; o[1] = S1; o[2] = S2; o[3] = 0.f;
        }
        __syncwarp();
    }
}

// Sagg gather (by src), deg, softmax, argmax, loss contributions.
__global__ void k_S2(const int* __restrict__ y) {
    __shared__ float rs[5][256];
    int i = blockIdx.x * 256 + threadIdx.x;
    float sl = 0.f, c0 = 0.f, c1 = 0.f, A0 = 0.f, A1 = 0.f;
    {
        int oc  = d_out_cnt[i];
        int cnt = oc < SLOTS ? oc : SLOTS;
        const int* lst = d_out_list + (size_t)i * SLOTS;
        const float4* Sf4 = (const float4*)d_Sf;
        float r0 = 0.f, r1 = 0.f, r2 = 0.f;
#pragma unroll 4
        for (int j = 0; j < cnt; j++) {
            float4 s = Sf4[lst[j]];
            r0 += s.x; r1 += s.y; r2 += s.z;
        }
        int ic = d_in_cnt[i];
        float deg = 0.5f * (float)(oc + ic);
        if (deg == 0.f) deg = 1.f;
        float inv = 1.f / deg;
        r0 *= inv; r1 *= inv; r2 *= inv;
        int am = 0; float mx = r0;
        if (r1 > mx) { am = 1; mx = r1; }
        if (r2 > mx) { am = 2; mx = r2; }
        float val = 1.f / (expf(r0 - mx) + expf(r1 - mx) + expf(r2 - mx));
        d_amax[i] = am;
        d_val[i]  = val;
        if (am < 2) {
            sl = val;
            int yb = y[i >> 9];
            float ce = log1pf(expf(val)) - (yb == am ? val : 0.f);
            if (yb == 0) { c0 = 1.f; A0 = ce; } else { c1 = 1.f; A1 = ce; }
        }
    }
    int t = threadIdx.x;
    rs[0][t] = sl; rs[1][t] = c0; rs[2][t] = c1; rs[3][t] = A0; rs[4][t] = A1;
    __syncthreads();
    for (int s = 128; s > 0; s >>= 1) {
        if (t < s) {
#pragma unroll
            for (int r = 0; r < 5; r++) rs[r][t] += rs[r][t + s];
        }
        __syncthreads();
    }
    if (t < 5) atomicAdd(&d_scal[t], rs[t][0]);
}

// pooling partials: 512 blocks = (graph b, quarter q). 384 thr =
// 96 float4-channels x 4 node-subgroups. float4 loads, high MLP.
__global__ void k_poolp() {
    int b = blockIdx.x >> 2, q = blockIdx.x & 3;
    __shared__ float vals[128];
    __shared__ int   ams[128];
    __shared__ float4 xps[2][4][96];
    int t = threadIdx.x;
    int base = b * 512 + q * 128;
    if (t < 128) { vals[t] = d_val[base + t]; ams[t] = d_amax[base + t]; }
    __syncthreads();

    int sub = t / 96, c4 = t - sub * 96;
    float4 av = ((const float4*)d_a)[c4];
    float4 bv = ((const float4*)d_bb)[c4];
    const float4* X4 = (const float4*)d_X;
    float4 acc0 = {0,0,0,0}, acc1 = {0,0,0,0};
#pragma unroll 8
    for (int i = 0; i < 32; i++) {
        int nl = sub * 32 + i;
        float v  = vals[nl];
        int   am = ams[nl];
        float4 xv = X4[(size_t)(base + nl) * 96 + c4];
        float4 xn;
        xn.x = fmaf(xv.x, av.x, bv.x);
        xn.y = fmaf(xv.y, av.y, bv.y);
        xn.z = fmaf(xv.z, av.z, bv.z);
        xn.w = fmaf(xv.w, av.w, bv.w);
        if (am == 0) {
            acc0.x = fmaf(v, xn.x, acc0.x); acc0.y = fmaf(v, xn.y, acc0.y);
            acc0.z = fmaf(v, xn.z, acc0.z); acc0.w = fmaf(v, xn.w, acc0.w);
        } else if (am == 1) {
            acc1.x = fmaf(v, xn.x, acc1.x); acc1.y = fmaf(v, xn.y, acc1.y);
            acc1.z = fmaf(v, xn.z, acc1.z); acc1.w = fmaf(v, xn.w, acc1.w);
        }
    }
    xps[0][sub][c4] = acc0;
    xps[1][sub][c4] = acc1;
    __syncthreads();
    if (t < 192) {
        int k = t / 96, c = t - k * 96;
        float4 s0 = xps[k][0][c], s1 = xps[k][1][c];
        float4 s2 = xps[k][2][c], s3 = xps[k][3][c];
        float4 s;
        s.x = (s0.x + s1.x) + (s2.x + s3.x);
        s.y = (s0.y + s1.y) + (s2.y + s3.y);
        s.z = (s0.z + s1.z) + (s2.z + s3.z);
        s.w = (s0.w + s1.w) + (s2.w + s3.w);
        ((float4*)d_xpart)[((b * 2 + k) * 4 + q) * 96 + c] = s;
    }
}

// reduce pooling partials + lin_pool + classification head + (block 0) loss.
__global__ void k_head(const float* __restrict__ Wp,
                       const float* __restrict__ W1, const float* __restrict__ b1,
                       const float* __restrict__ W2, const float* __restrict__ b2,
                       float* __restrict__ out, int lossIdx) {
    int b = blockIdx.x, t = threadIdx.x;   // 384 threads
    __shared__ float xp[2][C3];
    __shared__ float xf[32];
    __shared__ float h[128];
    __shared__ float lg[2];
#pragma unroll
    for (int k = 0; k < 2; k++) {
        const float* p = d_xpart + ((b * 2 + k) * 4) * C3 + t;
        xp[k][t] = (p[0] + p[C3]) + (p[2 * C3] + p[3 * C3]);
    }
    __syncthreads();
    if (t < 32) {
        int kk = t >> 4, o = t & 15;
        float s = 0.f;
        for (int c = 0; c < C3; c++) s = fmaf(xp[kk][c], Wp[c * 16 + o], s);
        xf[t] = s;
    }
    __syncthreads();
    if (t < 128) {
        float acc = b1[t];
#pragma unroll
        for (int i = 0; i < 32; i++) acc = fmaf(xf[i], W1[i * 128 + t], acc);
        h[t] = fmaxf(acc, 0.f);
    }
    __syncthreads();
    if (t < 64) {
        int c = t >> 5, l = t & 31;
        float p = 0.f;
        for (int j = l; j < 128; j += 32) p = fmaf(h[j], W2[j * 2 + c], p);
#pragma unroll
        for (int off = 16; off; off >>= 1) p += __shfl_xor_sync(0xffffffffu, p, off);
        if (l == 0) lg[c] = p + b2[c];
    }
    __syncthreads();
    if (t == 0) {
        float m   = fmaxf(lg[0], lg[1]);
        float lse = m + logf(expf(lg[0] - m) + expf(lg[1] - m));
        out[b * 2 + 0] = lg[0] - lse;
        out[b * 2 + 1] = lg[1] - lse;
    }
    if (b == 0 && t == 256) {
        float sl = d_scal[0], c0 = d_scal[1], c1 = d_scal[2];
        float A0 = d_scal[3], A1 = d_scal[4];
        float bc0 = 1.f + c0, bc1 = 1.f + c1;
        float wm  = fmaxf(bc0, bc1);
        float w0  = wm / (bc0 + 0.001f), w1 = wm / (bc1 + 0.001f);
        float den = fmaxf(w0 * c0 + w1 * c1, 1e-12f);
        float cel = (w0 * A0 + w1 * A1) / den;
        out[lossIdx] = 10.f * cel + 0.01f * (sl * (1.f / 128.f));
    }
}

// ---------------- launch ----------------
extern "C" void kernel_launch(void* const* d_in, const int* in_sizes, int n_in,
                              void* d_out, int out_size) {
    const float* x     = (const float*)d_in[0];
    const int*   ei    = (const int*)d_in[1];
    const int*   y     = (const int*)d_in[2];
    const float* W1    = (const float*)d_in[3];
    const float* b1    = (const float*)d_in[4];
    const float* W2    = (const float*)d_in[5];
    const float* b2    = (const float*)d_in[6];
    const float* W3    = (const float*)d_in[7];
    const float* b3    = (const float*)d_in[8];
    const float* gamma = (const float*)d_in[9];
    const float* beta  = (const float*)d_in[10];
    const float* kmat  = (const float*)d_in[11];
    const float* Wp    = (const float*)d_in[12];
    const float* l1W   = (const float*)d_in[13];
    const float* l1b   = (const float*)d_in[14];
    const float* l2W   = (const float*)d_in[15];
    const float* l2b   = (const float*)d_in[16];
    float* out = (float*)d_out;

    k_zero1<<<256, 256>>>();                       // 1
    k_fill<<<2048, 256>>>(ei);                     // 2
    k_zs<<<1, 32>>>();                             // 3
    k_gemm<<<512, 256>>>(x, 0, W1);                // 4  <- ncu capture (gemm)
    k_agg<<<AGG_GRID, 256>>>(b1, 0);               // 5
    k_gemm<<<512, 256>>>(x, 1, W2);                // 6
    k_agg<<<AGG_GRID, 256>>>(b2, 128);             // 7
    k_gemm<<<512, 256>>>(x, 2, W3);                // 8
    k_agg<<<AGG_GRID, 256>>>(b3, 256);             // 9

    k_bn<<<49, 256>>>(gamma, beta, kmat);          // 10
    k_dist<<<2048, 256>>>(kmat);                   // 11
    k_S2<<<256, 256>>>(y);                         // 12
    k_poolp<<<512, 384>>>();                       // 13
    k_head<<<128, 384>>>(Wp, l1W, l1b, l2W, l2b, out, out_size - 1);  // 14
}